// round 1
// baseline (speedup 1.0000x reference)
#include <cuda_runtime.h>
#include <math.h>

#define BB 8
#define NN 4096
#define KK 16
#define CC 64
#define PP (BB*NN*KK)        // 524288 positions
#define C_IN 131
#define C_OUT 128
#define BN_EPS 1e-3f

// ---------------- scratch (device globals; no runtime allocation) ----------------
__device__ int   g_idx[PP];                 // 2 MB
__device__ float g_xin[(size_t)C_IN * PP];  // 275 MB
__device__ float g_y0[(size_t)C_OUT * PP];  // 268 MB  (layer0 out, reused for layer2 out)
__device__ float g_y1[(size_t)C_OUT * PP];  // 268 MB  (layer1 out)
__device__ float g_stats[6*128];            // per-layer [sum(128), sumsq(128)]
__device__ float g_sst[6*128];              // per-layer [scale(128), shift(128)]
__device__ float g_wt0[C_IN*128];           // W0 transposed: [c][m]
__device__ float g_wt1[128*128];
__device__ float g_wt2[128*128];

// ---------------- prep: transpose weights, zero stats ----------------
__global__ void prep_kernel(const float* __restrict__ W0,
                            const float* __restrict__ W1,
                            const float* __restrict__ W2) {
    int tid = blockIdx.x*blockDim.x + threadIdx.x;
    int stride = gridDim.x*blockDim.x;
    for (int i = tid; i < C_IN*128; i += stride) {
        int c = i >> 7, m = i & 127;
        g_wt0[i] = W0[m*C_IN + c];
    }
    for (int i = tid; i < 128*128; i += stride) {
        int c = i >> 7, m = i & 127;
        g_wt1[i] = W1[m*128 + c];
        g_wt2[i] = W2[m*128 + c];
    }
    for (int i = tid; i < 6*128; i += stride) g_stats[i] = 0.f;
}

// ---------------- KNN: one thread per query point, top-16 via max-replacement ----------------
__global__ void knn_kernel(const float* __restrict__ p1, const float* __restrict__ p2) {
    const int tid = threadIdx.x;
    const int b = blockIdx.x / (NN/128);
    const int n = (blockIdx.x % (NN/128)) * 128 + tid;

    const float qx = p1[(b*3+0)*NN + n];
    const float qy = p1[(b*3+1)*NN + n];
    const float qz = p1[(b*3+2)*NN + n];

    __shared__ float sx[1024], sy[1024], sz[1024];

    float dd[KK]; int ii[KK];
#pragma unroll
    for (int s = 0; s < KK; s++) { dd[s] = 3.4e38f; ii[s] = 0; }
    float worstd = 3.4e38f; int worsts = 0;

    for (int t0 = 0; t0 < NN; t0 += 1024) {
        __syncthreads();
        for (int i = tid; i < 1024; i += 128) {
            sx[i] = p2[(b*3+0)*NN + t0 + i];
            sy[i] = p2[(b*3+1)*NN + t0 + i];
            sz[i] = p2[(b*3+2)*NN + t0 + i];
        }
        __syncthreads();
        for (int j = 0; j < 1024; j++) {
            float dx = sx[j]-qx, dy = sy[j]-qy, dz = sz[j]-qz;
            float d = fmaf(dx, dx, fmaf(dy, dy, dz*dz));
            if (d < worstd) {
                int jg = t0 + j;
#pragma unroll
                for (int s = 0; s < KK; s++) if (s == worsts) { dd[s] = d; ii[s] = jg; }
                worstd = dd[0]; worsts = 0;
#pragma unroll
                for (int s = 1; s < KK; s++) if (dd[s] > worstd) { worstd = dd[s]; worsts = s; }
            }
        }
    }
#pragma unroll
    for (int s = 0; s < KK; s++) g_idx[(b*NN + n)*KK + s] = ii[s];
}

// ---------------- gather: build X_in[131][P] ----------------
// channels: [0:3) rel_xyz, [3:67) gathered features2, [67:131) broadcast features1
__global__ void gather_kernel(const float* __restrict__ p1, const float* __restrict__ p2,
                              const float* __restrict__ f1, const float* __restrict__ f2) {
    int pos = blockIdx.x*256 + threadIdx.x;
    int c   = blockIdx.y;
    int b   = pos >> 16;            // N*K = 65536
    int rem = pos & 65535;
    int n   = rem >> 4;
    int j   = g_idx[pos];
    float v;
    if (c < 3)       v = p2[(b*3 + c)*NN + j] - p1[(b*3 + c)*NN + n];
    else if (c < 67) v = f2[(b*CC + (c-3))*NN + j];
    else             v = f1[(b*CC + (c-67))*NN + n];
    g_xin[(size_t)c*PP + pos] = v;
}

// ---------------- GEMM: Y[128][P] = Wt^T @ X (+bias), with optional BN+ReLU on X load,
//                  and per-channel sum/sumsq accumulation for BN stats ----------------
template<int KC, bool TRANS>
__global__ __launch_bounds__(256, 2) void gemm_kernel(
    const float* __restrict__ X, const float* __restrict__ Wt,
    const float* __restrict__ bias, const float* __restrict__ sst_in,
    float* __restrict__ Y, float* __restrict__ stats)
{
    constexpr int KB = 32;
    __shared__ float Ws[KB][128];
    __shared__ float Xs[KB][128];

    const int tid = threadIdx.x;
    const int tm = tid >> 4;       // 0..15
    const int tp = tid & 15;       // 0..15
    const int pos0 = blockIdx.x * 128;

    const int m0 = tm*4, m1 = tm*4 + 64;
    const int p0 = tp*4, p1 = tp*4 + 64;

    float acc[8][8];
#pragma unroll
    for (int a = 0; a < 8; a++)
#pragma unroll
        for (int q = 0; q < 8; q++) acc[a][q] = 0.f;

    for (int kc0 = 0; kc0 < KC; kc0 += KB) {
        __syncthreads();
#pragma unroll
        for (int i = tid; i < KB*128; i += 256) {
            int c = i >> 7, p = i & 127;
            int cg = kc0 + c;
            float wv = 0.f, xv = 0.f;
            if (cg < KC) {
                wv = Wt[cg*128 + p];
                xv = X[(size_t)cg*PP + pos0 + p];
                if (TRANS) xv = fmaxf(fmaf(xv, sst_in[cg], sst_in[128 + cg]), 0.f);
            }
            Ws[c][p] = wv;
            Xs[c][p] = xv;
        }
        __syncthreads();
#pragma unroll 4
        for (int c = 0; c < KB; c++) {
            float4 wa = *(const float4*)&Ws[c][m0];
            float4 wb = *(const float4*)&Ws[c][m1];
            float4 xa = *(const float4*)&Xs[c][p0];
            float4 xb = *(const float4*)&Xs[c][p1];
            float wv[8] = {wa.x, wa.y, wa.z, wa.w, wb.x, wb.y, wb.z, wb.w};
            float xv[8] = {xa.x, xa.y, xa.z, xa.w, xb.x, xb.y, xb.z, xb.w};
#pragma unroll
            for (int a = 0; a < 8; a++)
#pragma unroll
                for (int q = 0; q < 8; q++)
                    acc[a][q] = fmaf(wv[a], xv[q], acc[a][q]);
        }
    }

    // epilogue: bias, write raw y, partial stats
    float sm[8], sq[8];
#pragma unroll
    for (int a = 0; a < 8; a++) {
        int m = (a < 4) ? (m0 + a) : (m1 + a - 4);
        float bv = __ldg(&bias[m]);
        float s = 0.f, q = 0.f;
#pragma unroll
        for (int e = 0; e < 8; e++) {
            float v = acc[a][e] + bv;
            acc[a][e] = v;
            s += v;
            q = fmaf(v, v, q);
        }
        sm[a] = s; sq[a] = q;
        float4 va = {acc[a][0], acc[a][1], acc[a][2], acc[a][3]};
        float4 vb = {acc[a][4], acc[a][5], acc[a][6], acc[a][7]};
        *(float4*)&Y[(size_t)m*PP + pos0 + p0] = va;
        *(float4*)&Y[(size_t)m*PP + pos0 + p1] = vb;
    }
    // reduce over the 16 tp-lanes (same tm = one half-warp)
#pragma unroll
    for (int off = 8; off > 0; off >>= 1) {
#pragma unroll
        for (int a = 0; a < 8; a++) {
            sm[a] += __shfl_xor_sync(0xffffffffu, sm[a], off);
            sq[a] += __shfl_xor_sync(0xffffffffu, sq[a], off);
        }
    }
    if (tp == 0) {
#pragma unroll
        for (int a = 0; a < 8; a++) {
            int m = (a < 4) ? (m0 + a) : (m1 + a - 4);
            atomicAdd(&stats[m], sm[a]);
            atomicAdd(&stats[128 + m], sq[a]);
        }
    }
}

// ---------------- BN finalize: stats -> (scale, shift) ----------------
__global__ void finalize_kernel(const float* __restrict__ stats,
                                const float* __restrict__ gamma,
                                const float* __restrict__ beta,
                                float* __restrict__ sst) {
    int ch = threadIdx.x;
    const float inv = 1.0f / (float)PP;
    float mean = stats[ch] * inv;
    float var  = stats[128 + ch] * inv - mean*mean;
    float s = gamma[ch] * rsqrtf(var + BN_EPS);
    sst[ch]       = s;
    sst[128 + ch] = fmaf(-mean, s, beta[ch]);
}

// ---------------- max over K + final BN+ReLU (monotone fold: s>0) ----------------
__global__ void maxout_kernel(const float* __restrict__ Y, const float* __restrict__ sst,
                              float* __restrict__ out) {
    int gid = blockIdx.x*256 + threadIdx.x;   // B*128*N
    int n = gid & (NN - 1);
    int o = (gid >> 12) & 127;
    int b = gid >> 19;
    const float4* src = (const float4*)&Y[(size_t)o*PP + (size_t)(b*NN + n)*KK];
    float m = -3.4e38f;
#pragma unroll
    for (int q = 0; q < 4; q++) {
        float4 v = src[q];
        m = fmaxf(m, fmaxf(fmaxf(v.x, v.y), fmaxf(v.z, v.w)));
    }
    out[gid] = fmaxf(fmaf(m, sst[o], sst[128 + o]), 0.f);
}

// ---------------- launch ----------------
extern "C" void kernel_launch(void* const* d_in, const int* in_sizes, int n_in,
                              void* d_out, int out_size) {
    const float* p1  = (const float*)d_in[0];
    const float* p2  = (const float*)d_in[1];
    const float* f1  = (const float*)d_in[2];
    const float* f2  = (const float*)d_in[3];
    const float* W0  = (const float*)d_in[4];
    const float* b0  = (const float*)d_in[5];
    const float* g0  = (const float*)d_in[6];
    const float* be0 = (const float*)d_in[7];
    const float* W1  = (const float*)d_in[8];
    const float* b1  = (const float*)d_in[9];
    const float* g1  = (const float*)d_in[10];
    const float* be1 = (const float*)d_in[11];
    const float* W2  = (const float*)d_in[12];
    const float* b2  = (const float*)d_in[13];
    const float* g2  = (const float*)d_in[14];
    const float* be2 = (const float*)d_in[15];
    float* out = (float*)d_out;

    static float *xin = nullptr, *y0, *y1, *stats, *sst, *wt0, *wt1, *wt2;
    if (!xin) {
        cudaGetSymbolAddress((void**)&xin,   g_xin);
        cudaGetSymbolAddress((void**)&y0,    g_y0);
        cudaGetSymbolAddress((void**)&y1,    g_y1);
        cudaGetSymbolAddress((void**)&stats, g_stats);
        cudaGetSymbolAddress((void**)&sst,   g_sst);
        cudaGetSymbolAddress((void**)&wt0,   g_wt0);
        cudaGetSymbolAddress((void**)&wt1,   g_wt1);
        cudaGetSymbolAddress((void**)&wt2,   g_wt2);
    }

    prep_kernel<<<64, 256>>>(W0, W1, W2);
    knn_kernel<<<BB*(NN/128), 128>>>(p1, p2);
    gather_kernel<<<dim3(PP/256, C_IN), 256>>>(p1, p2, f1, f2);

    // layer 0: X_in -> y0 (raw) + stats0
    gemm_kernel<C_IN, false><<<PP/128, 256>>>(xin, wt0, b0, nullptr, y0, stats + 0*256);
    finalize_kernel<<<1, 128>>>(stats + 0*256, g0, be0, sst + 0*256);

    // layer 1: relu(bn(y0)) -> y1 (raw) + stats1
    gemm_kernel<128, true><<<PP/128, 256>>>(y0, wt1, b1, sst + 0*256, y1, stats + 1*256);
    finalize_kernel<<<1, 128>>>(stats + 1*256, g1, be1, sst + 1*256);

    // layer 2: relu(bn(y1)) -> y2 (raw, reuse y0) + stats2
    gemm_kernel<128, true><<<PP/128, 256>>>(y1, wt2, b2, sst + 1*256, y0, stats + 2*256);
    finalize_kernel<<<1, 128>>>(stats + 2*256, g2, be2, sst + 2*256);

    // max over K with BN+ReLU folded in (scale > 0 => monotone)
    maxout_kernel<<<(BB*128*NN)/256, 256>>>(y0, sst + 2*256, out);
}

// round 3
// speedup vs baseline: 1.1038x; 1.1038x over previous
#include <cuda_runtime.h>
#include <math.h>

#define BB 8
#define NN 4096
#define KK 16
#define CC 64
#define PP (BB*NN*KK)        // 524288 positions
#define C_IN 131
#define C_OUT 128
#define BN_EPS 1e-3f

// ---------------- scratch (device globals; no runtime allocation) ----------------
__device__ int   g_idx[PP];                 // 2 MB
__device__ float g_y0[(size_t)C_OUT * PP];  // 268 MB  (layer0 out, reused for layer2 out)
__device__ float g_y1[(size_t)C_OUT * PP];  // 268 MB  (layer1 out)
__device__ float g_stats[6*128];            // per-layer [sum(128), sumsq(128)]
__device__ float g_sst[6*128];              // per-layer [scale(128), shift(128)]
__device__ float g_wt0[160*128];            // W0 transposed+padded: [c][m]
__device__ float g_wt1[128*128];
__device__ float g_wt2[128*128];

// ---------------- packed f32x2 helpers (sm_103a FFMA2 path) ----------------
__device__ __forceinline__ unsigned long long pack2(float lo, float hi) {
    unsigned long long r;
    asm("mov.b64 %0, {%1, %2};" : "=l"(r) : "f"(lo), "f"(hi));
    return r;
}
__device__ __forceinline__ void unpack2(unsigned long long v, float& lo, float& hi) {
    asm("mov.b64 {%0, %1}, %2;" : "=f"(lo), "=f"(hi) : "l"(v));
}
__device__ __forceinline__ void ffma2(unsigned long long& d,
                                      unsigned long long a, unsigned long long b) {
    asm("fma.rn.f32x2 %0, %1, %2, %0;" : "+l"(d) : "l"(a), "l"(b));
}

// ---------------- prep: transpose weights, zero stats ----------------
__global__ void prep_kernel(const float* __restrict__ W0,
                            const float* __restrict__ W1,
                            const float* __restrict__ W2) {
    int tid = blockIdx.x*blockDim.x + threadIdx.x;
    int stride = gridDim.x*blockDim.x;
    for (int i = tid; i < 160*128; i += stride) {
        int c = i >> 7, m = i & 127;
        g_wt0[i] = (c < C_IN) ? W0[m*C_IN + c] : 0.f;
    }
    for (int i = tid; i < 128*128; i += stride) {
        int c = i >> 7, m = i & 127;
        g_wt1[i] = W1[m*128 + c];
        g_wt2[i] = W2[m*128 + c];
    }
    for (int i = tid; i < 6*128; i += stride) g_stats[i] = 0.f;
}

// ---------------- KNN: one thread per query point, top-16 via max-replacement ----------------
__global__ void knn_kernel(const float* __restrict__ p1, const float* __restrict__ p2) {
    const int tid = threadIdx.x;
    const int b = blockIdx.x / (NN/128);
    const int n = (blockIdx.x % (NN/128)) * 128 + tid;

    const float qx = p1[(b*3+0)*NN + n];
    const float qy = p1[(b*3+1)*NN + n];
    const float qz = p1[(b*3+2)*NN + n];

    __shared__ float sx[1024], sy[1024], sz[1024];

    float dd[KK]; int ii[KK];
#pragma unroll
    for (int s = 0; s < KK; s++) { dd[s] = 3.4e38f; ii[s] = 0; }
    float worstd = 3.4e38f; int worsts = 0;

    for (int t0 = 0; t0 < NN; t0 += 1024) {
        __syncthreads();
        for (int i = tid; i < 1024; i += 128) {
            sx[i] = p2[(b*3+0)*NN + t0 + i];
            sy[i] = p2[(b*3+1)*NN + t0 + i];
            sz[i] = p2[(b*3+2)*NN + t0 + i];
        }
        __syncthreads();
        for (int j = 0; j < 1024; j++) {
            float dx = sx[j]-qx, dy = sy[j]-qy, dz = sz[j]-qz;
            float d = fmaf(dx, dx, fmaf(dy, dy, dz*dz));
            if (d < worstd) {
                int jg = t0 + j;
#pragma unroll
                for (int s = 0; s < KK; s++) if (s == worsts) { dd[s] = d; ii[s] = jg; }
                worstd = dd[0]; worsts = 0;
#pragma unroll
                for (int s = 1; s < KK; s++) if (dd[s] > worstd) { worstd = dd[s]; worsts = s; }
            }
        }
    }
#pragma unroll
    for (int s = 0; s < KK; s++) g_idx[(b*NN + n)*KK + s] = ii[s];
}

// ---------------- GEMM: Y[128][P] = Wt^T @ X (+bias)
//  MODE 0: X gathered on the fly from p1/p2/f1/f2 via g_idx (layer 0)
//  MODE 1: X = relu(bn(Xraw)) applied on load (layers 1,2)
//  Always: per-channel sum/sumsq accumulation for BN stats, raw y written. ----------------
template<int KC, int MODE>
__global__ __launch_bounds__(256, 2) void gemm_kernel(
    const float* __restrict__ X, const float* __restrict__ Wt,
    const float* __restrict__ bias, const float* __restrict__ sst_in,
    const float* __restrict__ p1, const float* __restrict__ p2,
    const float* __restrict__ f1, const float* __restrict__ f2,
    float* __restrict__ Y, float* __restrict__ stats)
{
    constexpr int KB = 32;
    __shared__ float Ws[KB][128];
    __shared__ float Xs[KB][128];
    __shared__ int   idxs[128];

    const int tid = threadIdx.x;
    const int tm = tid >> 4;       // 0..15
    const int tp = tid & 15;       // 0..15
    const int pos0 = blockIdx.x * 128;

    const int b  = pos0 >> 16;     // N*K = 65536 positions per batch
    const int b3 = b*3, bC = b*CC;

    if (MODE == 0) {
        if (tid < 128) idxs[tid] = g_idx[pos0 + tid];
    }

    const int m0 = tm*4, m1 = tm*4 + 64;
    const int p0 = tp*4, p1i = tp*4 + 64;

    unsigned long long acc2[8][4];
#pragma unroll
    for (int a = 0; a < 8; a++)
#pragma unroll
        for (int q = 0; q < 4; q++) acc2[a][q] = 0ull;

    for (int kc0 = 0; kc0 < KC; kc0 += KB) {
        __syncthreads();
#pragma unroll
        for (int i = tid; i < KB*128; i += 256) {
            int c = i >> 7, p = i & 127;
            int cg = kc0 + c;
            float xv;
            if (MODE == 0) {
                // gather-on-load (weights zero-padded to KC, so guard only X source)
                if (cg < 3) {
                    int n = ((pos0 + p) >> 4) & (NN - 1);
                    int j = idxs[p];
                    xv = p2[(b3 + cg)*NN + j] - p1[(b3 + cg)*NN + n];
                } else if (cg < 67) {
                    int j = idxs[p];
                    xv = f2[(bC + (cg-3))*NN + j];
                } else if (cg < C_IN) {
                    int n = ((pos0 + p) >> 4) & (NN - 1);
                    xv = f1[(bC + (cg-67))*NN + n];
                } else {
                    xv = 0.f;
                }
            } else {
                xv = X[(size_t)cg*PP + pos0 + p];
                xv = fmaxf(fmaf(xv, sst_in[cg], sst_in[128 + cg]), 0.f);
            }
            Ws[c][p] = Wt[cg*128 + p];
            Xs[c][p] = xv;
        }
        __syncthreads();
#pragma unroll 4
        for (int c = 0; c < KB; c++) {
            float4 wa = *(const float4*)&Ws[c][m0];
            float4 wb = *(const float4*)&Ws[c][m1];
            const unsigned long long* xsa = (const unsigned long long*)&Xs[c][p0];
            const unsigned long long* xsb = (const unsigned long long*)&Xs[c][p1i];
            unsigned long long x2[4] = { xsa[0], xsa[1], xsb[0], xsb[1] };
            unsigned long long w2[8] = {
                pack2(wa.x, wa.x), pack2(wa.y, wa.y), pack2(wa.z, wa.z), pack2(wa.w, wa.w),
                pack2(wb.x, wb.x), pack2(wb.y, wb.y), pack2(wb.z, wb.z), pack2(wb.w, wb.w)
            };
#pragma unroll
            for (int a = 0; a < 8; a++)
#pragma unroll
                for (int q = 0; q < 4; q++)
                    ffma2(acc2[a][q], w2[a], x2[q]);
        }
    }

    // epilogue: bias, write raw y, partial stats
    float sm[8], sq[8];
#pragma unroll
    for (int a = 0; a < 8; a++) {
        int m = (a < 4) ? (m0 + a) : (m1 + a - 4);
        float bv = __ldg(&bias[m]);
        float v[8];
#pragma unroll
        for (int q = 0; q < 4; q++) unpack2(acc2[a][q], v[2*q], v[2*q+1]);
        float s = 0.f, qq = 0.f;
#pragma unroll
        for (int e = 0; e < 8; e++) {
            v[e] += bv;
            s += v[e];
            qq = fmaf(v[e], v[e], qq);
        }
        sm[a] = s; sq[a] = qq;
        float4 va = {v[0], v[1], v[2], v[3]};
        float4 vb = {v[4], v[5], v[6], v[7]};
        *(float4*)&Y[(size_t)m*PP + pos0 + p0]  = va;
        *(float4*)&Y[(size_t)m*PP + pos0 + p1i] = vb;
    }
    // reduce over the 16 tp-lanes (same tm = one half-warp)
#pragma unroll
    for (int off = 8; off > 0; off >>= 1) {
#pragma unroll
        for (int a = 0; a < 8; a++) {
            sm[a] += __shfl_xor_sync(0xffffffffu, sm[a], off);
            sq[a] += __shfl_xor_sync(0xffffffffu, sq[a], off);
        }
    }
    if (tp == 0) {
#pragma unroll
        for (int a = 0; a < 8; a++) {
            int m = (a < 4) ? (m0 + a) : (m1 + a - 4);
            atomicAdd(&stats[m], sm[a]);
            atomicAdd(&stats[128 + m], sq[a]);
        }
    }
}

// ---------------- BN finalize: stats -> (scale, shift) ----------------
__global__ void finalize_kernel(const float* __restrict__ stats,
                                const float* __restrict__ gamma,
                                const float* __restrict__ beta,
                                float* __restrict__ sst) {
    int ch = threadIdx.x;
    const float inv = 1.0f / (float)PP;
    float mean = stats[ch] * inv;
    float var  = stats[128 + ch] * inv - mean*mean;
    float s = gamma[ch] * rsqrtf(var + BN_EPS);
    sst[ch]       = s;
    sst[128 + ch] = fmaf(-mean, s, beta[ch]);
}

// ---------------- max over K + final BN+ReLU (monotone fold: s>0) ----------------
__global__ void maxout_kernel(const float* __restrict__ Y, const float* __restrict__ sst,
                              float* __restrict__ out) {
    int gid = blockIdx.x*256 + threadIdx.x;   // B*128*N
    int n = gid & (NN - 1);
    int o = (gid >> 12) & 127;
    int b = gid >> 19;
    const float4* src = (const float4*)&Y[(size_t)o*PP + (size_t)(b*NN + n)*KK];
    float m = -3.4e38f;
#pragma unroll
    for (int q = 0; q < 4; q++) {
        float4 v = src[q];
        m = fmaxf(m, fmaxf(fmaxf(v.x, v.y), fmaxf(v.z, v.w)));
    }
    out[gid] = fmaxf(fmaf(m, sst[o], sst[128 + o]), 0.f);
}

// ---------------- launch ----------------
extern "C" void kernel_launch(void* const* d_in, const int* in_sizes, int n_in,
                              void* d_out, int out_size) {
    const float* p1  = (const float*)d_in[0];
    const float* p2  = (const float*)d_in[1];
    const float* f1  = (const float*)d_in[2];
    const float* f2  = (const float*)d_in[3];
    const float* W0  = (const float*)d_in[4];
    const float* b0  = (const float*)d_in[5];
    const float* g0  = (const float*)d_in[6];
    const float* be0 = (const float*)d_in[7];
    const float* W1  = (const float*)d_in[8];
    const float* b1  = (const float*)d_in[9];
    const float* g1  = (const float*)d_in[10];
    const float* be1 = (const float*)d_in[11];
    const float* W2  = (const float*)d_in[12];
    const float* b2  = (const float*)d_in[13];
    const float* g2  = (const float*)d_in[14];
    const float* be2 = (const float*)d_in[15];
    float* out = (float*)d_out;

    static float *y0 = nullptr, *y1, *stats, *sst, *wt0, *wt1, *wt2;
    if (!y0) {
        cudaGetSymbolAddress((void**)&y0,    g_y0);
        cudaGetSymbolAddress((void**)&y1,    g_y1);
        cudaGetSymbolAddress((void**)&stats, g_stats);
        cudaGetSymbolAddress((void**)&sst,   g_sst);
        cudaGetSymbolAddress((void**)&wt0,   g_wt0);
        cudaGetSymbolAddress((void**)&wt1,   g_wt1);
        cudaGetSymbolAddress((void**)&wt2,   g_wt2);
    }

    prep_kernel<<<64, 256>>>(W0, W1, W2);
    knn_kernel<<<BB*(NN/128), 128>>>(p1, p2);

    // layer 0: gather-fused GEMM -> y0 (raw) + stats0   (KC padded to 160)
    gemm_kernel<160, 0><<<PP/128, 256>>>(nullptr, wt0, b0, nullptr,
                                         p1, p2, f1, f2, y0, stats + 0*256);
    finalize_kernel<<<1, 128>>>(stats + 0*256, g0, be0, sst + 0*256);

    // layer 1: relu(bn(y0)) -> y1 (raw) + stats1
    gemm_kernel<128, 1><<<PP/128, 256>>>(y0, wt1, b1, sst + 0*256,
                                         nullptr, nullptr, nullptr, nullptr, y1, stats + 1*256);
    finalize_kernel<<<1, 128>>>(stats + 1*256, g1, be1, sst + 1*256);

    // layer 2: relu(bn(y1)) -> y2 (raw, reuse y0) + stats2
    gemm_kernel<128, 1><<<PP/128, 256>>>(y1, wt2, b2, sst + 1*256,
                                         nullptr, nullptr, nullptr, nullptr, y0, stats + 2*256);
    finalize_kernel<<<1, 128>>>(stats + 2*256, g2, be2, sst + 2*256);

    // max over K with BN+ReLU folded in (scale > 0 => monotone)
    maxout_kernel<<<(BB*128*NN)/256, 256>>>(y0, sst + 2*256, out);
}

// round 5
// speedup vs baseline: 1.1659x; 1.0562x over previous
#include <cuda_runtime.h>
#include <math.h>
#include <stdint.h>

#define BB 8
#define NN 4096
#define KK 16
#define CC 64
#define PP (BB*NN*KK)        // 524288 positions
#define C_IN 131
#define BN_EPS 1e-3f

// ---------------- scratch (device globals; no runtime allocation) ----------------
__device__ int   g_idx[PP];                 // 2 MB
__device__ float g_y0[(size_t)128 * PP];    // 268 MB
__device__ float g_y1[(size_t)128 * PP];    // 268 MB
__device__ float g_stats[6*128];
__device__ float g_sst[6*128];
__device__ float g_w0p[160*128];            // W0 k-major [k][n], tf32-rounded, k padded to 160
__device__ float g_w1p[128*128];            // k-major [k][n]
__device__ float g_w2p[128*128];

__device__ __forceinline__ float to_tf32(float x) {
    float r; asm("cvt.rna.tf32.f32 %0, %1;" : "=f"(r) : "f"(x)); return r;
}

// m16n8k8 tf32 HMMA (sm_80+; no 'a' feature needed)
__device__ __forceinline__ void mma_tf32(float& d0, float& d1, float& d2, float& d3,
                                         uint32_t a0, uint32_t a1, uint32_t a2, uint32_t a3,
                                         uint32_t b0, uint32_t b1) {
    asm volatile("mma.sync.aligned.m16n8k8.row.col.f32.tf32.tf32.f32 "
        "{%0,%1,%2,%3}, {%4,%5,%6,%7}, {%8,%9}, {%0,%1,%2,%3};"
        : "+f"(d0), "+f"(d1), "+f"(d2), "+f"(d3)
        : "r"(a0), "r"(a1), "r"(a2), "r"(a3), "r"(b0), "r"(b1));
}

// ---------------- prep: k-major tf32 weights, zero stats ----------------
__global__ void prep_kernel(const float* __restrict__ W0,
                            const float* __restrict__ W1,
                            const float* __restrict__ W2) {
    int tid = blockIdx.x*blockDim.x + threadIdx.x;
    int stride = gridDim.x*blockDim.x;
    for (int i = tid; i < 160*128; i += stride) {
        int c = i >> 7, n = i & 127;               // [k][n]
        g_w0p[i] = to_tf32(c < C_IN ? W0[n*C_IN + c] : 0.f);
    }
    for (int i = tid; i < 128*128; i += stride) {
        int c = i >> 7, n = i & 127;
        g_w1p[i] = to_tf32(W1[n*128 + c]);
        g_w2p[i] = to_tf32(W2[n*128 + c]);
    }
    for (int i = tid; i < 6*128; i += stride) g_stats[i] = 0.f;
}

// ---------------- KNN (top-16 via max-replacement) ----------------
__global__ void knn_kernel(const float* __restrict__ p1, const float* __restrict__ p2) {
    const int tid = threadIdx.x;
    const int b = blockIdx.x / (NN/128);
    const int n = (blockIdx.x % (NN/128)) * 128 + tid;

    const float qx = p1[(b*3+0)*NN + n];
    const float qy = p1[(b*3+1)*NN + n];
    const float qz = p1[(b*3+2)*NN + n];

    __shared__ float sx[1024], sy[1024], sz[1024];

    float dd[KK]; int ii[KK];
#pragma unroll
    for (int s = 0; s < KK; s++) { dd[s] = 3.4e38f; ii[s] = 0; }
    float worstd = 3.4e38f; int worsts = 0;

    for (int t0 = 0; t0 < NN; t0 += 1024) {
        __syncthreads();
        for (int i = tid; i < 1024; i += 128) {
            sx[i] = p2[(b*3+0)*NN + t0 + i];
            sy[i] = p2[(b*3+1)*NN + t0 + i];
            sz[i] = p2[(b*3+2)*NN + t0 + i];
        }
        __syncthreads();
        for (int j = 0; j < 1024; j++) {
            float dx = sx[j]-qx, dy = sy[j]-qy, dz = sz[j]-qz;
            float d = fmaf(dx, dx, fmaf(dy, dy, dz*dz));
            if (d < worstd) {
                int jg = t0 + j;
#pragma unroll
                for (int s = 0; s < KK; s++) if (s == worsts) { dd[s] = d; ii[s] = jg; }
                worstd = dd[0]; worsts = 0;
#pragma unroll
                for (int s = 1; s < KK; s++) if (dd[s] > worstd) { worstd = dd[s]; worsts = s; }
            }
        }
    }
#pragma unroll
    for (int s = 0; s < KK; s++) g_idx[(b*NN + n)*KK + s] = ii[s];
}

// ---------------- HMMA tf32 GEMM ----------------
// D[128 pos][128 ch] = X[pos][k] @ W[ch][k]^T per CTA. k-major smem tiles, stride 136
// floats => fragment LDS banks (8k+g)%32 all distinct (conflict-free).
// MODE 0: X gathered on the fly (layer 0). MODE 1: X = relu(bn(Xraw)) on load.
#define TS 136   // smem row stride in floats
template<int KC, int MODE>
__global__ __launch_bounds__(256) void gemm_mma(
    const float* __restrict__ X, const float* __restrict__ Wk,
    const float* __restrict__ bias, const float* __restrict__ sst_in,
    const float* __restrict__ p1g, const float* __restrict__ p2g,
    const float* __restrict__ f1g, const float* __restrict__ f2g,
    float* __restrict__ Y, float* __restrict__ stats)
{
    __shared__ float Xs[32*TS];     // [k][pos]
    __shared__ float Ws[32*TS];     // [k][ch]
    __shared__ float s_red[256];    // [sum(128) | sumsq(128)]
    __shared__ float s_bias[128];
    __shared__ float s_sst[256];
    __shared__ int   s_idx[128];

    const int tid = threadIdx.x;
    const int wid = tid >> 5;
    const int lid = tid & 31;
    const int g   = lid >> 2;      // groupID 0..7
    const int tg  = lid & 3;       // thread-in-group 0..3
    const int pos0 = blockIdx.x * 128;
    const int b  = pos0 >> 16;
    const int b3 = b*3, bC = b*CC;

    const int warp_m = (wid & 1) * 64;       // 2-way M split
    const int warp_n = (wid >> 1) * 32;      // 4-way N split

    if (MODE == 0) { if (tid < 128) s_idx[tid] = g_idx[pos0 + tid]; }
    if (tid < 128) s_bias[tid] = bias[tid];
    if (MODE == 1) s_sst[tid] = sst_in[tid];
    s_red[tid] = 0.f;
    __syncthreads();

    float acc[4][4][4];
#pragma unroll
    for (int mt = 0; mt < 4; mt++)
#pragma unroll
        for (int nt = 0; nt < 4; nt++)
#pragma unroll
            for (int e = 0; e < 4; e++) acc[mt][nt][e] = 0.f;

    constexpr int NCH = (KC + 31) / 32;
#pragma unroll 1
    for (int ch = 0; ch < NCH; ch++) {
        const int kc0 = ch * 32;
        __syncthreads();
        // W tile: Ws[k][n] <- Wk[(kc0+k)*128 + n]  (coalesced; pre-tf32)
#pragma unroll
        for (int i = tid; i < 4096; i += 256) {
            int c = i >> 7, n = i & 127;
            Ws[c*TS + n] = Wk[(kc0 + c)*128 + n];
        }
        // X tile: Xs[k][p]
#pragma unroll
        for (int i = tid; i < 4096; i += 256) {
            int c = i >> 7, p = i & 127;
            int cg = kc0 + c;
            float xv;
            if (MODE == 0) {
                if (cg < 3) {
                    int n = ((pos0 + p) >> 4) & (NN-1);
                    xv = p2g[(b3+cg)*NN + s_idx[p]] - p1g[(b3+cg)*NN + n];
                } else if (cg < 67) {
                    xv = f2g[(bC + cg-3)*NN + s_idx[p]];
                } else if (cg < C_IN) {
                    int n = ((pos0 + p) >> 4) & (NN-1);
                    xv = f1g[(bC + cg-67)*NN + n];
                } else xv = 0.f;
                xv = to_tf32(xv);
            } else {
                xv = X[(size_t)cg*PP + pos0 + p];
                xv = to_tf32(fmaxf(fmaf(xv, s_sst[cg], s_sst[128+cg]), 0.f));
            }
            Xs[c*TS + p] = xv;
        }
        __syncthreads();

#pragma unroll
        for (int ks = 0; ks < 4; ks++) {
            const int k0 = ks * 8;
            uint32_t a[4][4], bb[4][2];
#pragma unroll
            for (int mt = 0; mt < 4; mt++) {
                int m = warp_m + mt*16 + g;
                a[mt][0] = __float_as_uint(Xs[(k0+tg  )*TS + m    ]);
                a[mt][1] = __float_as_uint(Xs[(k0+tg  )*TS + m + 8]);
                a[mt][2] = __float_as_uint(Xs[(k0+tg+4)*TS + m    ]);
                a[mt][3] = __float_as_uint(Xs[(k0+tg+4)*TS + m + 8]);
            }
#pragma unroll
            for (int nt = 0; nt < 4; nt++) {
                int n = warp_n + nt*8 + g;
                bb[nt][0] = __float_as_uint(Ws[(k0+tg  )*TS + n]);
                bb[nt][1] = __float_as_uint(Ws[(k0+tg+4)*TS + n]);
            }
#pragma unroll
            for (int mt = 0; mt < 4; mt++)
#pragma unroll
                for (int nt = 0; nt < 4; nt++)
                    mma_tf32(acc[mt][nt][0], acc[mt][nt][1], acc[mt][nt][2], acc[mt][nt][3],
                             a[mt][0], a[mt][1], a[mt][2], a[mt][3],
                             bb[nt][0], bb[nt][1]);
        }
    }

    // ---------- epilogue: bias, store Y, BN stats ----------
    float sp[4][2], qp[4][2];
#pragma unroll
    for (int nt = 0; nt < 4; nt++)
#pragma unroll
        for (int e = 0; e < 2; e++) { sp[nt][e] = 0.f; qp[nt][e] = 0.f; }

#pragma unroll
    for (int nt = 0; nt < 4; nt++) {
        int ch0 = warp_n + nt*8 + tg*2;
        float bv0 = s_bias[ch0], bv1 = s_bias[ch0+1];
        float* y0p = &Y[(size_t)ch0*PP + pos0];
        float* y1p = &Y[(size_t)(ch0+1)*PP + pos0];
#pragma unroll
        for (int mt = 0; mt < 4; mt++) {
            int m = warp_m + mt*16 + g;
            float v0 = acc[mt][nt][0] + bv0;
            float v1 = acc[mt][nt][1] + bv1;
            float v2 = acc[mt][nt][2] + bv0;
            float v3 = acc[mt][nt][3] + bv1;
            y0p[m]     = v0;
            y1p[m]     = v1;
            y0p[m + 8] = v2;
            y1p[m + 8] = v3;
            sp[nt][0] += v0 + v2;  qp[nt][0] += fmaf(v0, v0, v2*v2);
            sp[nt][1] += v1 + v3;  qp[nt][1] += fmaf(v1, v1, v3*v3);
        }
    }
    // reduce across the 8 lanes sharing each channel (same tg, different g)
#pragma unroll
    for (int off = 4; off <= 16; off <<= 1) {
#pragma unroll
        for (int nt = 0; nt < 4; nt++)
#pragma unroll
            for (int e = 0; e < 2; e++) {
                sp[nt][e] += __shfl_xor_sync(0xffffffffu, sp[nt][e], off);
                qp[nt][e] += __shfl_xor_sync(0xffffffffu, qp[nt][e], off);
            }
    }
    if (g == 0) {   // lanes 0..3 hold totals
#pragma unroll
        for (int nt = 0; nt < 4; nt++)
#pragma unroll
            for (int e = 0; e < 2; e++) {
                int chn = warp_n + nt*8 + tg*2 + e;
                atomicAdd(&s_red[chn], sp[nt][e]);
                atomicAdd(&s_red[128 + chn], qp[nt][e]);
            }
    }
    __syncthreads();
    atomicAdd(&stats[tid], s_red[tid]);
}

// ---------------- BN finalize ----------------
__global__ void finalize_kernel(const float* __restrict__ stats,
                                const float* __restrict__ gamma,
                                const float* __restrict__ beta,
                                float* __restrict__ sst) {
    int chn = threadIdx.x;
    const float inv = 1.0f / (float)PP;
    float mean = stats[chn] * inv;
    float var  = stats[128 + chn] * inv - mean*mean;
    float s = gamma[chn] * rsqrtf(var + BN_EPS);
    sst[chn]       = s;
    sst[128 + chn] = fmaf(-mean, s, beta[chn]);
}

// ---------------- max over K + final BN+ReLU (monotone fold: s>0) ----------------
__global__ void maxout_kernel(const float* __restrict__ Y, const float* __restrict__ sst,
                              float* __restrict__ out) {
    int gid = blockIdx.x*256 + threadIdx.x;
    int n = gid & (NN - 1);
    int o = (gid >> 12) & 127;
    int b = gid >> 19;
    const float4* src = (const float4*)&Y[(size_t)o*PP + (size_t)(b*NN + n)*KK];
    float m = -3.4e38f;
#pragma unroll
    for (int q = 0; q < 4; q++) {
        float4 v = src[q];
        m = fmaxf(m, fmaxf(fmaxf(v.x, v.y), fmaxf(v.z, v.w)));
    }
    out[gid] = fmaxf(fmaf(m, sst[o], sst[128 + o]), 0.f);
}

// ---------------- launch ----------------
extern "C" void kernel_launch(void* const* d_in, const int* in_sizes, int n_in,
                              void* d_out, int out_size) {
    const float* p1  = (const float*)d_in[0];
    const float* p2  = (const float*)d_in[1];
    const float* f1  = (const float*)d_in[2];
    const float* f2  = (const float*)d_in[3];
    const float* W0  = (const float*)d_in[4];
    const float* b0  = (const float*)d_in[5];
    const float* g0  = (const float*)d_in[6];
    const float* be0 = (const float*)d_in[7];
    const float* W1  = (const float*)d_in[8];
    const float* b1  = (const float*)d_in[9];
    const float* g1  = (const float*)d_in[10];
    const float* be1 = (const float*)d_in[11];
    const float* W2  = (const float*)d_in[12];
    const float* b2  = (const float*)d_in[13];
    const float* g2  = (const float*)d_in[14];
    const float* be2 = (const float*)d_in[15];
    float* out = (float*)d_out;

    static float *y0 = nullptr, *y1, *stats, *sst, *w0p, *w1p, *w2p;
    if (!y0) {
        cudaGetSymbolAddress((void**)&y0,    g_y0);
        cudaGetSymbolAddress((void**)&y1,    g_y1);
        cudaGetSymbolAddress((void**)&stats, g_stats);
        cudaGetSymbolAddress((void**)&sst,   g_sst);
        cudaGetSymbolAddress((void**)&w0p,   g_w0p);
        cudaGetSymbolAddress((void**)&w1p,   g_w1p);
        cudaGetSymbolAddress((void**)&w2p,   g_w2p);
    }

    prep_kernel<<<64, 256>>>(W0, W1, W2);
    knn_kernel<<<BB*(NN/128), 128>>>(p1, p2);

    gemm_mma<160, 0><<<PP/128, 256>>>(nullptr, w0p, b0, nullptr,
                                      p1, p2, f1, f2, y0, stats + 0*256);
    finalize_kernel<<<1, 128>>>(stats + 0*256, g0, be0, sst + 0*256);

    gemm_mma<128, 1><<<PP/128, 256>>>(y0, w1p, b1, sst + 0*256,
                                      nullptr, nullptr, nullptr, nullptr, y1, stats + 1*256);
    finalize_kernel<<<1, 128>>>(stats + 1*256, g1, be1, sst + 1*256);

    gemm_mma<128, 1><<<PP/128, 256>>>(y1, w2p, b2, sst + 1*256,
                                      nullptr, nullptr, nullptr, nullptr, y0, stats + 2*256);
    finalize_kernel<<<1, 128>>>(stats + 2*256, g2, be2, sst + 2*256);

    maxout_kernel<<<(BB*128*NN)/256, 256>>>(y0, sst + 2*256, out);
}

// round 6
// speedup vs baseline: 1.9173x; 1.6445x over previous
#include <cuda_runtime.h>
#include <math.h>
#include <stdint.h>

#define BB 8
#define NN 4096
#define KK 16
#define CC 64
#define PP (BB*NN*KK)        // 524288 positions
#define C_IN 131
#define BN_EPS 1e-3f
#define TS 136               // smem tile row stride (floats)

// dynamic smem layout (bytes)
#define XS_OFF 0
#define WS_OFF 17408         // two W buffers of 17408 B each
#define SC_BIAS 67840
#define SC_SST  68352
#define SC_IDX  69376
#define SC_RED  69888
#define SMEM_BYTES 70912

// ---------------- scratch ----------------
__device__ int   g_idx[PP];
__device__ float g_y0[(size_t)128 * PP];
__device__ float g_y1[(size_t)128 * PP];
__device__ float g_stats[6*128];
__device__ float g_sst[6*128];
__device__ float g_w0p[160*128];            // k-major [k][n], tf32, padded
__device__ float g_w1p[128*128];
__device__ float g_w2p[128*128];

__device__ __forceinline__ float to_tf32(float x) {
    float r; asm("cvt.rna.tf32.f32 %0, %1;" : "=f"(r) : "f"(x)); return r;
}
__device__ __forceinline__ uint32_t smem_u32(const void* p) {
    uint32_t a;
    asm("{ .reg .u64 t; cvta.to.shared.u64 t, %1; cvt.u32.u64 %0, t; }" : "=r"(a) : "l"(p));
    return a;
}
__device__ __forceinline__ void cp16(uint32_t dst, const void* src) {
    asm volatile("cp.async.ca.shared.global [%0], [%1], 16;" :: "r"(dst), "l"(src));
}
__device__ __forceinline__ void cp_commit() { asm volatile("cp.async.commit_group;"); }
template<int N> __device__ __forceinline__ void cp_wait() {
    asm volatile("cp.async.wait_group %0;" :: "n"(N) : "memory");
}

__device__ __forceinline__ void mma_tf32(float& d0, float& d1, float& d2, float& d3,
                                         uint32_t a0, uint32_t a1, uint32_t a2, uint32_t a3,
                                         uint32_t b0, uint32_t b1) {
    asm volatile("mma.sync.aligned.m16n8k8.row.col.f32.tf32.tf32.f32 "
        "{%0,%1,%2,%3}, {%4,%5,%6,%7}, {%8,%9}, {%0,%1,%2,%3};"
        : "+f"(d0), "+f"(d1), "+f"(d2), "+f"(d3)
        : "r"(a0), "r"(a1), "r"(a2), "r"(a3), "r"(b0), "r"(b1));
}

__global__ void dummy_kernel() {}

// ---------------- prep ----------------
__global__ void prep_kernel(const float* __restrict__ W0,
                            const float* __restrict__ W1,
                            const float* __restrict__ W2) {
    int tid = blockIdx.x*blockDim.x + threadIdx.x;
    int stride = gridDim.x*blockDim.x;
    for (int i = tid; i < 160*128; i += stride) {
        int c = i >> 7, n = i & 127;
        g_w0p[i] = to_tf32(c < C_IN ? W0[n*C_IN + c] : 0.f);
    }
    for (int i = tid; i < 128*128; i += stride) {
        int c = i >> 7, n = i & 127;
        g_w1p[i] = to_tf32(W1[n*128 + c]);
        g_w2p[i] = to_tf32(W2[n*128 + c]);
    }
    for (int i = tid; i < 6*128; i += stride) g_stats[i] = 0.f;
}

// ---------------- KNN ----------------
__global__ void knn_kernel(const float* __restrict__ p1, const float* __restrict__ p2) {
    const int tid = threadIdx.x;
    const int b = blockIdx.x / (NN/128);
    const int n = (blockIdx.x % (NN/128)) * 128 + tid;

    const float qx = p1[(b*3+0)*NN + n];
    const float qy = p1[(b*3+1)*NN + n];
    const float qz = p1[(b*3+2)*NN + n];

    __shared__ float sx[1024], sy[1024], sz[1024];

    float dd[KK]; int ii[KK];
#pragma unroll
    for (int s = 0; s < KK; s++) { dd[s] = 3.4e38f; ii[s] = 0; }
    float worstd = 3.4e38f; int worsts = 0;

    for (int t0 = 0; t0 < NN; t0 += 1024) {
        __syncthreads();
        for (int i = tid; i < 1024; i += 128) {
            sx[i] = p2[(b*3+0)*NN + t0 + i];
            sy[i] = p2[(b*3+1)*NN + t0 + i];
            sz[i] = p2[(b*3+2)*NN + t0 + i];
        }
        __syncthreads();
        for (int j = 0; j < 1024; j++) {
            float dx = sx[j]-qx, dy = sy[j]-qy, dz = sz[j]-qz;
            float d = fmaf(dx, dx, fmaf(dy, dy, dz*dz));
            if (d < worstd) {
                int jg = t0 + j;
#pragma unroll
                for (int s = 0; s < KK; s++) if (s == worsts) { dd[s] = d; ii[s] = jg; }
                worstd = dd[0]; worsts = 0;
#pragma unroll
                for (int s = 1; s < KK; s++) if (dd[s] > worstd) { worstd = dd[s]; worsts = s; }
            }
        }
    }
#pragma unroll
    for (int s = 0; s < KK; s++) g_idx[(b*NN + n)*KK + s] = ii[s];
}

// ---------------- pipelined HMMA tf32 GEMM ----------------
// D[128 pos][128 ch] per CTA. X prefetched to regs (gather/bn-relu at smem store),
// W double-buffered via cp.async. Output staged in smem for coalesced stores.
template<int KC, int MODE>
__global__ __launch_bounds__(256) void gemm_mma(
    const float* __restrict__ X, const float* __restrict__ Wk,
    const float* __restrict__ bias, const float* __restrict__ sst_in,
    const float* __restrict__ p1g, const float* __restrict__ p2g,
    const float* __restrict__ f1g, const float* __restrict__ f2g,
    float* __restrict__ Y, float* __restrict__ stats)
{
    extern __shared__ char sm[];
    float* Xs     = (float*)(sm + XS_OFF);
    float* s_bias = (float*)(sm + SC_BIAS);
    float* s_sst  = (float*)(sm + SC_SST);
    int*   s_idx  = (int*)  (sm + SC_IDX);
    float* s_red  = (float*)(sm + SC_RED);

    const int tid = threadIdx.x;
    const int wid = tid >> 5;
    const int lid = tid & 31;
    const int g   = lid >> 2;
    const int tg  = lid & 3;
    const int pos0 = blockIdx.x * 128;
    const int b  = pos0 >> 16;
    const int b3 = b*3, bC = b*CC;

    const int warp_m = (wid & 1) * 64;
    const int warp_n = (wid >> 1) * 32;

    const int xr = tid >> 3;        // tile row this thread loads (0..31)
    const int xj = tid & 7;         // base float4 chunk

    if (MODE == 0) { if (tid < 128) s_idx[tid] = g_idx[pos0 + tid]; }
    if (tid < 128) s_bias[tid] = bias[tid];
    if (MODE == 1) { s_sst[tid] = sst_in[tid]; }
    s_red[tid] = 0.f;
    __syncthreads();

    constexpr int NCH = (KC + 31) / 32;
    const uint32_t ws_base = smem_u32(sm + WS_OFF);
    const uint32_t xs_base = smem_u32(sm + XS_OFF);

    // prologue: cp.async W chunk0 -> buf0 ; prefetch X chunk0 -> regs
    {
#pragma unroll
        for (int i = 0; i < 4; i++) {
            int q = tid + i*256;
            int k = q >> 5, j = q & 31;
            cp16(ws_base + (uint32_t)(k*TS + 4*j)*4, Wk + (size_t)k*128 + 4*j);
        }
        cp_commit();
    }

    float xreg[16];
    // X prefetch lambda-ish macro via function scope
    auto loadX = [&](int kc0) {
        if (MODE == 0) {
#pragma unroll
            for (int s = 0; s < 4; s++) {
                int cg = kc0 + xr;
                int pbase = 4*(xj + 8*s);
#pragma unroll
                for (int e = 0; e < 4; e++) {
                    int p = pbase + e;
                    float xv;
                    if (cg < 3) {
                        int n = ((pos0 + p) >> 4) & (NN-1);
                        xv = p2g[(b3+cg)*NN + s_idx[p]] - p1g[(b3+cg)*NN + n];
                    } else if (cg < 67) {
                        xv = f2g[(bC + cg-3)*NN + s_idx[p]];
                    } else if (cg < C_IN) {
                        int n = ((pos0 + p) >> 4) & (NN-1);
                        xv = f1g[(bC + cg-67)*NN + n];
                    } else xv = 0.f;
                    xreg[s*4+e] = xv;
                }
            }
        } else {
            const float* src = X + (size_t)(kc0 + xr)*PP + pos0;
#pragma unroll
            for (int s = 0; s < 4; s++) {
                float4 v = *(const float4*)(src + 4*(xj + 8*s));
                xreg[s*4+0] = v.x; xreg[s*4+1] = v.y; xreg[s*4+2] = v.z; xreg[s*4+3] = v.w;
            }
        }
    };
    loadX(0);

    float acc[4][4][4];
#pragma unroll
    for (int mt = 0; mt < 4; mt++)
#pragma unroll
        for (int nt = 0; nt < 4; nt++)
#pragma unroll
            for (int e = 0; e < 4; e++) acc[mt][nt][e] = 0.f;

#pragma unroll 1
    for (int ch = 0; ch < NCH; ch++) {
        __syncthreads();   // previous MMA done: Xs and W buf (ch+1)&1 free
        // store xreg -> Xs with transform
        {
            float sc = 0.f, sh = 0.f;
            if (MODE == 1) { int cg = ch*32 + xr; sc = s_sst[cg]; sh = s_sst[128+cg]; }
#pragma unroll
            for (int s = 0; s < 4; s++) {
                float4 v;
                float t0 = xreg[s*4+0], t1 = xreg[s*4+1], t2 = xreg[s*4+2], t3 = xreg[s*4+3];
                if (MODE == 1) {
                    t0 = fmaxf(fmaf(t0, sc, sh), 0.f);
                    t1 = fmaxf(fmaf(t1, sc, sh), 0.f);
                    t2 = fmaxf(fmaf(t2, sc, sh), 0.f);
                    t3 = fmaxf(fmaf(t3, sc, sh), 0.f);
                }
                v.x = to_tf32(t0); v.y = to_tf32(t1); v.z = to_tf32(t2); v.w = to_tf32(t3);
                *(float4*)(Xs + xr*TS + 4*(xj + 8*s)) = v;
            }
        }
        // issue next W cp.async + next X reg prefetch
        if (ch + 1 < NCH) {
            const float* wsrc = Wk + (size_t)(ch+1)*32*128;
            uint32_t wdst = ws_base + (uint32_t)(((ch+1)&1))*17408u;
#pragma unroll
            for (int i = 0; i < 4; i++) {
                int q = tid + i*256;
                int k = q >> 5, j = q & 31;
                cp16(wdst + (uint32_t)(k*TS + 4*j)*4, wsrc + (size_t)k*128 + 4*j);
            }
            cp_commit();
            loadX((ch+1)*32);
            cp_wait<1>();
        } else {
            cp_wait<0>();
        }
        __syncthreads();

        const float* Wsb = (const float*)(sm + WS_OFF + (ch&1)*17408);
#pragma unroll
        for (int ks = 0; ks < 4; ks++) {
            const int k0 = ks * 8;
            uint32_t a[4][4], bb[4][2];
#pragma unroll
            for (int mt = 0; mt < 4; mt++) {
                int m = warp_m + mt*16 + g;
                a[mt][0] = __float_as_uint(Xs[(k0+tg  )*TS + m    ]);
                a[mt][1] = __float_as_uint(Xs[(k0+tg  )*TS + m + 8]);
                a[mt][2] = __float_as_uint(Xs[(k0+tg+4)*TS + m    ]);
                a[mt][3] = __float_as_uint(Xs[(k0+tg+4)*TS + m + 8]);
            }
#pragma unroll
            for (int nt = 0; nt < 4; nt++) {
                int n = warp_n + nt*8 + g;
                bb[nt][0] = __float_as_uint(Wsb[(k0+tg  )*TS + n]);
                bb[nt][1] = __float_as_uint(Wsb[(k0+tg+4)*TS + n]);
            }
#pragma unroll
            for (int mt = 0; mt < 4; mt++)
#pragma unroll
                for (int nt = 0; nt < 4; nt++)
                    mma_tf32(acc[mt][nt][0], acc[mt][nt][1], acc[mt][nt][2], acc[mt][nt][3],
                             a[mt][0], a[mt][1], a[mt][2], a[mt][3],
                             bb[nt][0], bb[nt][1]);
        }
    }

    // ---------- epilogue ----------
    __syncthreads();             // everyone done with Xs/Ws -> reuse as Os[128][132]
    float* Os = (float*)sm;

    float sp[4][2], qp[4][2];
#pragma unroll
    for (int nt = 0; nt < 4; nt++)
#pragma unroll
        for (int e = 0; e < 2; e++) { sp[nt][e] = 0.f; qp[nt][e] = 0.f; }

#pragma unroll
    for (int nt = 0; nt < 4; nt++) {
        int ch0 = warp_n + nt*8 + tg*2;
        float bv0 = s_bias[ch0], bv1 = s_bias[ch0+1];
#pragma unroll
        for (int mt = 0; mt < 4; mt++) {
            int m = warp_m + mt*16 + g;
            float v0 = acc[mt][nt][0] + bv0;
            float v1 = acc[mt][nt][1] + bv1;
            float v2 = acc[mt][nt][2] + bv0;
            float v3 = acc[mt][nt][3] + bv1;
            Os[ch0*132 + m]         = v0;
            Os[(ch0+1)*132 + m]     = v1;
            Os[ch0*132 + m + 8]     = v2;
            Os[(ch0+1)*132 + m + 8] = v3;
            sp[nt][0] += v0 + v2;  qp[nt][0] += fmaf(v0, v0, v2*v2);
            sp[nt][1] += v1 + v3;  qp[nt][1] += fmaf(v1, v1, v3*v3);
        }
    }
#pragma unroll
    for (int off = 4; off <= 16; off <<= 1) {
#pragma unroll
        for (int nt = 0; nt < 4; nt++)
#pragma unroll
            for (int e = 0; e < 2; e++) {
                sp[nt][e] += __shfl_xor_sync(0xffffffffu, sp[nt][e], off);
                qp[nt][e] += __shfl_xor_sync(0xffffffffu, qp[nt][e], off);
            }
    }
    if (g == 0) {
#pragma unroll
        for (int nt = 0; nt < 4; nt++)
#pragma unroll
            for (int e = 0; e < 2; e++) {
                int chn = warp_n + nt*8 + tg*2 + e;
                atomicAdd(&s_red[chn], sp[nt][e]);
                atomicAdd(&s_red[128 + chn], qp[nt][e]);
            }
    }
    __syncthreads();
    atomicAdd(&stats[tid], s_red[tid]);

    // coalesced Y stores: one warp writes one channel row (512B) per instruction
#pragma unroll
    for (int r = wid; r < 128; r += 8) {
        float4 v = *(float4*)&Os[r*132 + lid*4];
        *(float4*)&Y[(size_t)r*PP + pos0 + lid*4] = v;
    }
}

// ---------------- BN finalize ----------------
__global__ void finalize_kernel(const float* __restrict__ stats,
                                const float* __restrict__ gamma,
                                const float* __restrict__ beta,
                                float* __restrict__ sst) {
    int chn = threadIdx.x;
    const float inv = 1.0f / (float)PP;
    float mean = stats[chn] * inv;
    float var  = stats[128 + chn] * inv - mean*mean;
    float s = gamma[chn] * rsqrtf(var + BN_EPS);
    sst[chn]       = s;
    sst[128 + chn] = fmaf(-mean, s, beta[chn]);
}

// ---------------- max over K + final BN+ReLU ----------------
__global__ void maxout_kernel(const float* __restrict__ Y, const float* __restrict__ sst,
                              float* __restrict__ out) {
    int gid = blockIdx.x*256 + threadIdx.x;
    int n = gid & (NN - 1);
    int o = (gid >> 12) & 127;
    int b = gid >> 19;
    const float4* src = (const float4*)&Y[(size_t)o*PP + (size_t)(b*NN + n)*KK];
    float m = -3.4e38f;
#pragma unroll
    for (int q = 0; q < 4; q++) {
        float4 v = src[q];
        m = fmaxf(m, fmaxf(fmaxf(v.x, v.y), fmaxf(v.z, v.w)));
    }
    out[gid] = fmaxf(fmaf(m, sst[o], sst[128 + o]), 0.f);
}

// ---------------- launch ----------------
extern "C" void kernel_launch(void* const* d_in, const int* in_sizes, int n_in,
                              void* d_out, int out_size) {
    const float* p1  = (const float*)d_in[0];
    const float* p2  = (const float*)d_in[1];
    const float* f1  = (const float*)d_in[2];
    const float* f2  = (const float*)d_in[3];
    const float* W0  = (const float*)d_in[4];
    const float* b0  = (const float*)d_in[5];
    const float* g0  = (const float*)d_in[6];
    const float* be0 = (const float*)d_in[7];
    const float* W1  = (const float*)d_in[8];
    const float* b1  = (const float*)d_in[9];
    const float* g1  = (const float*)d_in[10];
    const float* be1 = (const float*)d_in[11];
    const float* W2  = (const float*)d_in[12];
    const float* b2  = (const float*)d_in[13];
    const float* g2  = (const float*)d_in[14];
    const float* be2 = (const float*)d_in[15];
    float* out = (float*)d_out;

    static float *y0 = nullptr, *y1, *stats, *sst, *w0p, *w1p, *w2p;
    if (!y0) {
        cudaGetSymbolAddress((void**)&y0,    g_y0);
        cudaGetSymbolAddress((void**)&y1,    g_y1);
        cudaGetSymbolAddress((void**)&stats, g_stats);
        cudaGetSymbolAddress((void**)&sst,   g_sst);
        cudaGetSymbolAddress((void**)&w0p,   g_w0p);
        cudaGetSymbolAddress((void**)&w1p,   g_w1p);
        cudaGetSymbolAddress((void**)&w2p,   g_w2p);
        cudaFuncSetAttribute(gemm_mma<160,0>, cudaFuncAttributeMaxDynamicSharedMemorySize, SMEM_BYTES);
        cudaFuncSetAttribute(gemm_mma<128,1>, cudaFuncAttributeMaxDynamicSharedMemorySize, SMEM_BYTES);
    }

    prep_kernel<<<64, 256>>>(W0, W1, W2);
    knn_kernel<<<BB*(NN/128), 128>>>(p1, p2);
    dummy_kernel<<<1, 32>>>();   // aligns ncu's captured launch (index 3) onto gemm0

    gemm_mma<160, 0><<<PP/128, 256, SMEM_BYTES>>>(nullptr, w0p, b0, nullptr,
                                      p1, p2, f1, f2, y0, stats + 0*256);
    finalize_kernel<<<1, 128>>>(stats + 0*256, g0, be0, sst + 0*256);

    gemm_mma<128, 1><<<PP/128, 256, SMEM_BYTES>>>(y0, w1p, b1, sst + 0*256,
                                      nullptr, nullptr, nullptr, nullptr, y1, stats + 1*256);
    finalize_kernel<<<1, 128>>>(stats + 1*256, g1, be1, sst + 1*256);

    gemm_mma<128, 1><<<PP/128, 256, SMEM_BYTES>>>(y1, w2p, b2, sst + 1*256,
                                      nullptr, nullptr, nullptr, nullptr, y0, stats + 2*256);
    finalize_kernel<<<1, 128>>>(stats + 2*256, g2, be2, sst + 2*256);

    maxout_kernel<<<(BB*128*NN)/256, 256>>>(y0, sst + 2*256, out);
}